// round 1
// baseline (speedup 1.0000x reference)
#include <cuda_runtime.h>
#include <math_constants.h>

#define NN 50000
#define EE 800000

// ---------------- scratch (static device globals; no allocation) ----------------
__device__ float g_hx  [NN * 64];   // x @ W1^T
__device__ float g_h2  [NN * 64];   // relu(GCN out)
__device__ float g_xl  [NN * 128];  // h2 @ Wl^T + bl
__device__ float g_xr  [NN * 128];  // h2 @ Wr^T + br
__device__ float g_skip[NN * 32];   // skip_gate*(x @ Ws^T + bs)
__device__ float g_lasum[NN];
__device__ int   g_cnt [NN];
__device__ float g_dinv[NN];
__device__ float g_loopattr[NN];
__device__ int   g_off [NN];
__device__ int   g_cur [NN];
__device__ int   g_csrc[EE];
__device__ float g_cw  [EE];

// ---------------- zero per-launch state ----------------
__global__ void zero_kernel() {
    int stride = gridDim.x * blockDim.x;
    for (int n = blockIdx.x * blockDim.x + threadIdx.x; n < NN; n += stride) {
        g_lasum[n] = 0.f;
        g_cnt[n] = 0;
        g_cur[n] = 0;
    }
}

// ---------------- generic GEMM: C[n,M] = A[n,64] @ W[M,64]^T, + bias, * scale ----------------
// Each thread owns one output column (W row in 64 registers), R rows per tile staged in smem.
template <int M, int R>
__global__ void gemm64(const float* __restrict__ A, const float* __restrict__ W,
                       const float* __restrict__ bias, const float* __restrict__ scale_ptr,
                       float* __restrict__ C, int n) {
    __shared__ float4 xs[R][16];
    int tx = threadIdx.x, ty = threadIdx.y;
    float w[64];
#pragma unroll
    for (int k = 0; k < 64; k++) w[k] = W[tx * 64 + k];
    float b  = bias ? bias[tx] : 0.f;
    float sc = scale_ptr ? *scale_ptr : 1.f;
    int tid = ty * M + tx;
    int ntiles = (n + R - 1) / R;
    for (int tile = blockIdx.x; tile < ntiles; tile += gridDim.x) {
        int row0 = tile * R;
        __syncthreads();
        for (int i = tid; i < R * 16; i += M * R) {
            int r = i >> 4, c = i & 15;
            int row = row0 + r;
            xs[r][c] = (row < n) ? reinterpret_cast<const float4*>(A)[row * 16 + c]
                                 : make_float4(0.f, 0.f, 0.f, 0.f);
        }
        __syncthreads();
        int row = row0 + ty;
        if (row < n) {
            float acc = 0.f;
#pragma unroll
            for (int c = 0; c < 16; c++) {
                float4 v = xs[ty][c];
                acc = fmaf(v.x, w[4 * c + 0], acc);
                acc = fmaf(v.y, w[4 * c + 1], acc);
                acc = fmaf(v.z, w[4 * c + 2], acc);
                acc = fmaf(v.w, w[4 * c + 3], acc);
            }
            C[row * M + tx] = (acc + b) * sc;
        }
    }
}

// ---------------- edge pass 1: weighted in-degree + count ----------------
__global__ void deg_kernel(const int* __restrict__ dst, const float* __restrict__ ew) {
    int stride = gridDim.x * blockDim.x;
    for (int e = blockIdx.x * blockDim.x + threadIdx.x; e < EE; e += stride) {
        int d = dst[e];
        atomicAdd(&g_lasum[d], ew[e]);
        atomicAdd(&g_cnt[d], 1);
    }
}

// ---------------- per-node stats: dinv = rsqrt(la_sum + 1), loop_attr = mean in-weight ----------------
__global__ void node_kernel() {
    int stride = gridDim.x * blockDim.x;
    for (int n = blockIdx.x * blockDim.x + threadIdx.x; n < NN; n += stride) {
        float ls = g_lasum[n];
        int c = g_cnt[n];
        g_dinv[n] = rsqrtf(ls + 1.0f);  // self-loop weight 1 => deg >= 1
        g_loopattr[n] = (c > 0) ? ls / (float)c : 0.f;
    }
}

// ---------------- exclusive scan of g_cnt -> g_off (single block) ----------------
__global__ void scan_kernel() {
    __shared__ int sums[1024];
    int t = threadIdx.x;
    const int CH = (NN + 1023) / 1024;
    int lo = t * CH, hi = min(lo + CH, NN);
    int s = 0;
    for (int i = lo; i < hi; i++) s += g_cnt[i];
    sums[t] = s;
    __syncthreads();
    for (int d = 1; d < 1024; d <<= 1) {
        int v = (t >= d) ? sums[t - d] : 0;
        __syncthreads();
        sums[t] += v;
        __syncthreads();
    }
    int run = (t > 0) ? sums[t - 1] : 0;
    for (int i = lo; i < hi; i++) {
        g_off[i] = run;
        run += g_cnt[i];
    }
}

// ---------------- edge pass 2: scatter into dst-sorted CSR ----------------
__global__ void csr_kernel(const int* __restrict__ src, const int* __restrict__ dst,
                           const float* __restrict__ ew) {
    int stride = gridDim.x * blockDim.x;
    for (int e = blockIdx.x * blockDim.x + threadIdx.x; e < EE; e += stride) {
        int d = dst[e];
        int p = g_off[d] + atomicAdd(&g_cur[d], 1);
        g_csrc[p] = src[e];
        g_cw[p] = ew[e];
    }
}

// ---------------- GCN aggregate (warp per node) + bias + relu -> h2 ----------------
__global__ void gcn_kernel(const float* __restrict__ b1) {
    int lane = threadIdx.x & 31;
    int warp = (blockIdx.x * blockDim.x + threadIdx.x) >> 5;
    int nwarps = (gridDim.x * blockDim.x) >> 5;
    for (int n = warp; n < NN; n += nwarps) {
        float dn = g_dinv[n];
        float a0 = g_hx[n * 64 + lane] * dn * dn;        // self loop, weight 1
        float a1 = g_hx[n * 64 + 32 + lane] * dn * dn;
        int beg = g_off[n], end = beg + g_cnt[n];
        for (int p = beg; p < end; p++) {
            int s = g_csrc[p];
            float nw = g_dinv[s] * g_cw[p] * dn;
            a0 = fmaf(g_hx[s * 64 + lane], nw, a0);
            a1 = fmaf(g_hx[s * 64 + 32 + lane], nw, a1);
        }
        g_h2[n * 64 + lane]      = fmaxf(a0 + b1[lane], 0.f);
        g_h2[n * 64 + 32 + lane] = fmaxf(a1 + b1[32 + lane], 0.f);
    }
}

// ---------------- GATv2 with online edge-softmax (warp per node, lane = channel) ----------------
__global__ void gat_kernel(const float* __restrict__ We, const float* __restrict__ att,
                           const float* __restrict__ bias_gat, float* __restrict__ out) {
    int lane = threadIdx.x & 31;
    int warp = (blockIdx.x * blockDim.x + threadIdx.x) >> 5;
    int nwarps = (gridDim.x * blockDim.x) >> 5;
    float we[4], at[4];
#pragma unroll
    for (int h = 0; h < 4; h++) {
        we[h] = We[h * 32 + lane];
        at[h] = att[h * 32 + lane];
    }
    for (int n = warp; n < NN; n += nwarps) {
        float xr[4];
#pragma unroll
        for (int h = 0; h < 4; h++) xr[h] = g_xr[n * 128 + h * 32 + lane];
        float acc[4] = {0.f, 0.f, 0.f, 0.f};
        float mh[4]  = {-CUDART_INF_F, -CUDART_INF_F, -CUDART_INF_F, -CUDART_INF_F};
        float lh[4]  = {0.f, 0.f, 0.f, 0.f};
        int beg = g_off[n], cnt = g_cnt[n];
        for (int p = beg; p <= beg + cnt; p++) {   // last iteration = self loop
            int s;
            float ea;
            if (p < beg + cnt) { s = g_csrc[p]; ea = g_cw[p]; }
            else               { s = n;         ea = g_loopattr[n]; }
#pragma unroll
            for (int h = 0; h < 4; h++) {
                float xlv = g_xl[s * 128 + h * 32 + lane];
                float mm = xlv + xr[h] + ea * we[h];
                mm = (mm > 0.f) ? mm : 0.2f * mm;   // leaky_relu(0.2)
                float al = mm * at[h];
#pragma unroll
                for (int off = 16; off > 0; off >>= 1)
                    al += __shfl_xor_sync(0xFFFFFFFFu, al, off);
                float nm = fmaxf(mh[h], al);
                float scale = __expf(mh[h] - nm);   // exp(-inf)=0 first iter
                float pv = __expf(al - nm);
                lh[h]  = lh[h] * scale + pv;
                acc[h] = acc[h] * scale + pv * xlv;
                mh[h]  = nm;
            }
        }
        float v = 0.f;
#pragma unroll
        for (int h = 0; h < 4; h++) v += acc[h] / (lh[h] + 1e-16f);
        out[n * 32 + lane] = 0.25f * v + bias_gat[lane] + g_skip[n * 32 + lane];
    }
}

// ---------------- launch ----------------
extern "C" void kernel_launch(void* const* d_in, const int* in_sizes, int n_in,
                              void* d_out, int out_size) {
    const float* x   = (const float*)d_in[0];
    const int*   ei  = (const int*)  d_in[1];
    const float* ew  = (const float*)d_in[2];
    const float* W1  = (const float*)d_in[3];
    const float* b1  = (const float*)d_in[4];
    const float* Wl  = (const float*)d_in[5];
    const float* bl  = (const float*)d_in[6];
    const float* Wr  = (const float*)d_in[7];
    const float* br  = (const float*)d_in[8];
    const float* We  = (const float*)d_in[9];
    const float* att = (const float*)d_in[10];
    const float* bg  = (const float*)d_in[11];
    const float* Ws  = (const float*)d_in[12];
    const float* bs  = (const float*)d_in[13];
    const float* sg  = (const float*)d_in[14];
    float* out = (float*)d_out;

    const int* src = ei;
    const int* dst = ei + EE;

    void *p_hx, *p_h2, *p_xl, *p_xr, *p_skip;
    cudaGetSymbolAddress(&p_hx, g_hx);
    cudaGetSymbolAddress(&p_h2, g_h2);
    cudaGetSymbolAddress(&p_xl, g_xl);
    cudaGetSymbolAddress(&p_xr, g_xr);
    cudaGetSymbolAddress(&p_skip, g_skip);

    zero_kernel<<<128, 256>>>();
    gemm64<64, 4><<<1024, dim3(64, 4)>>>(x, W1, nullptr, nullptr, (float*)p_hx, NN);
    gemm64<32, 8><<<1024, dim3(32, 8)>>>(x, Ws, bs, sg, (float*)p_skip, NN);
    deg_kernel<<<800, 256>>>(dst, ew);
    node_kernel<<<128, 256>>>();
    scan_kernel<<<1, 1024>>>();
    csr_kernel<<<800, 256>>>(src, dst, ew);
    gcn_kernel<<<1024, 256>>>(b1);
    gemm64<128, 2><<<1024, dim3(128, 2)>>>((const float*)p_h2, Wl, bl, nullptr, (float*)p_xl, NN);
    gemm64<128, 2><<<1024, dim3(128, 2)>>>((const float*)p_h2, Wr, br, nullptr, (float*)p_xr, NN);
    gat_kernel<<<1024, 256>>>(We, att, bg, out);
}

// round 2
// speedup vs baseline: 1.3379x; 1.3379x over previous
#include <cuda_runtime.h>
#include <math_constants.h>

#define NN 50000
#define EE 800000

// ---------------- scratch (static device globals; no allocation) ----------------
__device__ float g_hx  [NN * 64];   // x @ W1^T
__device__ float g_h2  [NN * 64];   // relu(GCN out)
__device__ float g_xl  [NN * 128];  // h2 @ Wl^T + bl
__device__ float g_xr  [NN * 128];  // h2 @ Wr^T + br
__device__ float g_skip[NN * 32];   // skip_gate*(x @ Ws^T + bs)
__device__ float g_lasum[NN];
__device__ int   g_cnt [NN];
__device__ float g_dinv[NN];
__device__ float g_loopattr[NN];
__device__ int   g_off [NN];
__device__ int   g_cur [NN];
__device__ int   g_csrc[EE];
__device__ float g_cw  [EE];

// ---------------- zero per-launch state ----------------
__global__ void zero_kernel() {
    int stride = gridDim.x * blockDim.x;
    for (int n = blockIdx.x * blockDim.x + threadIdx.x; n < NN; n += stride) {
        g_lasum[n] = 0.f;
        g_cnt[n] = 0;
        g_cur[n] = 0;
    }
}

// ---------------- GEMM: C[n,M] = A[n,64] @ W[M,64]^T, + bias, * scale ----------------
// Thread tx owns output column tx (weight row in 64 regs); R rows per tile, T row-threads,
// each thread computes R/T rows per tile (reusing the register weight column).
template <int M, int R, int T>
__global__ void gemm64(const float* __restrict__ A, const float* __restrict__ W,
                       const float* __restrict__ bias, const float* __restrict__ scale_ptr,
                       float* __restrict__ C, int n) {
    __shared__ float4 xs[R][16];
    const int tx = threadIdx.x, ty = threadIdx.y;
    float w[64];
#pragma unroll
    for (int k = 0; k < 64; k++) w[k] = W[tx * 64 + k];
    float b  = bias ? bias[tx] : 0.f;
    float sc = scale_ptr ? *scale_ptr : 1.f;
    const int tid = ty * M + tx;
    const int nthreads = M * T;
    const int ntiles = (n + R - 1) / R;
    for (int tile = blockIdx.x; tile < ntiles; tile += gridDim.x) {
        int row0 = tile * R;
        __syncthreads();
        for (int i = tid; i < R * 16; i += nthreads) {
            int r = i >> 4, c = i & 15;
            int row = row0 + r;
            xs[r][c] = (row < n) ? reinterpret_cast<const float4*>(A)[row * 16 + c]
                                 : make_float4(0.f, 0.f, 0.f, 0.f);
        }
        __syncthreads();
#pragma unroll
        for (int rr = 0; rr < R / T; rr++) {
            int r = rr * T + ty;
            int row = row0 + r;
            if (row < n) {
                float acc = 0.f;
#pragma unroll
                for (int c = 0; c < 16; c++) {
                    float4 v = xs[r][c];
                    acc = fmaf(v.x, w[4 * c + 0], acc);
                    acc = fmaf(v.y, w[4 * c + 1], acc);
                    acc = fmaf(v.z, w[4 * c + 2], acc);
                    acc = fmaf(v.w, w[4 * c + 3], acc);
                }
                C[row * M + tx] = (acc + b) * sc;
            }
        }
    }
}

// ---------------- edge pass 1: weighted in-degree + count ----------------
__global__ void deg_kernel(const int* __restrict__ dst, const float* __restrict__ ew) {
    int stride = gridDim.x * blockDim.x;
    for (int e = blockIdx.x * blockDim.x + threadIdx.x; e < EE; e += stride) {
        int d = dst[e];
        atomicAdd(&g_lasum[d], ew[e]);
        atomicAdd(&g_cnt[d], 1);
    }
}

// ---------------- per-node stats ----------------
__global__ void node_kernel() {
    int stride = gridDim.x * blockDim.x;
    for (int n = blockIdx.x * blockDim.x + threadIdx.x; n < NN; n += stride) {
        float ls = g_lasum[n];
        int c = g_cnt[n];
        g_dinv[n] = rsqrtf(ls + 1.0f);  // self-loop weight 1 => deg >= 1
        g_loopattr[n] = (c > 0) ? ls / (float)c : 0.f;
    }
}

// ---------------- exclusive scan of g_cnt -> g_off (single block) ----------------
__global__ void scan_kernel() {
    __shared__ int sums[1024];
    int t = threadIdx.x;
    const int CH = (NN + 1023) / 1024;
    int lo = t * CH, hi = min(lo + CH, NN);
    int s = 0;
    for (int i = lo; i < hi; i++) s += g_cnt[i];
    sums[t] = s;
    __syncthreads();
    for (int d = 1; d < 1024; d <<= 1) {
        int v = (t >= d) ? sums[t - d] : 0;
        __syncthreads();
        sums[t] += v;
        __syncthreads();
    }
    int run = (t > 0) ? sums[t - 1] : 0;
    for (int i = lo; i < hi; i++) {
        g_off[i] = run;
        run += g_cnt[i];
    }
}

// ---------------- edge pass 2: scatter into dst-sorted CSR ----------------
__global__ void csr_kernel(const int* __restrict__ src, const int* __restrict__ dst,
                           const float* __restrict__ ew) {
    int stride = gridDim.x * blockDim.x;
    for (int e = blockIdx.x * blockDim.x + threadIdx.x; e < EE; e += stride) {
        int d = dst[e];
        int p = g_off[d] + atomicAdd(&g_cur[d], 1);
        g_csrc[p] = src[e];
        g_cw[p] = ew[e];
    }
}

// ---------------- GCN aggregate (warp per node, float2 per lane) + bias + relu ----------------
__global__ void gcn_kernel(const float* __restrict__ b1) {
    int lane = threadIdx.x & 31;
    int warp = (blockIdx.x * blockDim.x + threadIdx.x) >> 5;
    int nwarps = (gridDim.x * blockDim.x) >> 5;
    const float2* __restrict__ hx2 = (const float2*)g_hx;
    float2 b = reinterpret_cast<const float2*>(b1)[lane];
    for (int n = warp; n < NN; n += nwarps) {
        float dn = g_dinv[n];
        float2 v = hx2[n * 32 + lane];
        float a0 = v.x * dn * dn;          // self loop, weight 1
        float a1 = v.y * dn * dn;
        int beg = g_off[n], end = beg + g_cnt[n];
        for (int p = beg; p < end; p++) {
            int s = g_csrc[p];
            float nw = g_dinv[s] * g_cw[p] * dn;
            float2 u = hx2[s * 32 + lane];
            a0 = fmaf(u.x, nw, a0);
            a1 = fmaf(u.y, nw, a1);
        }
        float2 o;
        o.x = fmaxf(a0 + b.x, 0.f);
        o.y = fmaxf(a1 + b.y, 0.f);
        reinterpret_cast<float2*>(g_h2)[n * 32 + lane] = o;
    }
}

// ---------------- GATv2: lane = (head h = lane>>3, quad q = lane&7), 4 channels/lane ----------------
// alpha dot-product: 4 reg FMAs + 3-shfl butterfly (covers all 4 heads at once).
// softmax without running max (|alpha| ~ O(1); shift-invariant => identical result).
__global__ void gat_kernel(const float* __restrict__ We, const float* __restrict__ att,
                           const float* __restrict__ bias_gat, float* __restrict__ out) {
    int lane = threadIdx.x & 31;
    int q = lane & 7;
    int h = lane >> 3;
    int warp = (blockIdx.x * blockDim.x + threadIdx.x) >> 5;
    int nwarps = (gridDim.x * blockDim.x) >> 5;
    const float4* __restrict__ xl4 = (const float4*)g_xl;   // [NN*32]
    const float4* __restrict__ xr4 = (const float4*)g_xr;
    float4 we4 = reinterpret_cast<const float4*>(We)[h * 8 + q];
    float4 at4 = reinterpret_cast<const float4*>(att)[h * 8 + q];
    float4 bg4 = reinterpret_cast<const float4*>(bias_gat)[q];

    for (int n = warp; n < NN; n += nwarps) {
        float4 xr = xr4[n * 32 + lane];
        float4 acc = make_float4(0.f, 0.f, 0.f, 0.f);
        float lsum = 0.f;
        int beg = g_off[n], cnt = g_cnt[n];
        // edges + final self-loop iteration
        for (int p = beg; p <= beg + cnt; p++) {
            int s; float ea;
            if (p < beg + cnt) { s = g_csrc[p]; ea = g_cw[p]; }
            else               { s = n;         ea = g_loopattr[n]; }
            float4 xlv = xl4[s * 32 + lane];
            float m0 = fmaf(ea, we4.x, xlv.x + xr.x); m0 = (m0 > 0.f) ? m0 : 0.2f * m0;
            float m1 = fmaf(ea, we4.y, xlv.y + xr.y); m1 = (m1 > 0.f) ? m1 : 0.2f * m1;
            float m2 = fmaf(ea, we4.z, xlv.z + xr.z); m2 = (m2 > 0.f) ? m2 : 0.2f * m2;
            float m3 = fmaf(ea, we4.w, xlv.w + xr.w); m3 = (m3 > 0.f) ? m3 : 0.2f * m3;
            float part = m0 * at4.x;
            part = fmaf(m1, at4.y, part);
            part = fmaf(m2, at4.z, part);
            part = fmaf(m3, at4.w, part);
            part += __shfl_xor_sync(0xFFFFFFFFu, part, 1);
            part += __shfl_xor_sync(0xFFFFFFFFu, part, 2);
            part += __shfl_xor_sync(0xFFFFFFFFu, part, 4);   // alpha for head h, uniform in group
            float pv = __expf(part);
            lsum += pv;
            acc.x = fmaf(pv, xlv.x, acc.x);
            acc.y = fmaf(pv, xlv.y, acc.y);
            acc.z = fmaf(pv, xlv.z, acc.z);
            acc.w = fmaf(pv, xlv.w, acc.w);
        }
        float inv = __fdividef(1.f, lsum);
        float r0 = acc.x * inv, r1 = acc.y * inv, r2 = acc.z * inv, r3 = acc.w * inv;
        // mean over heads: butterfly across groups (same q position)
#pragma unroll
        for (int off = 8; off <= 16; off <<= 1) {
            r0 += __shfl_xor_sync(0xFFFFFFFFu, r0, off);
            r1 += __shfl_xor_sync(0xFFFFFFFFu, r1, off);
            r2 += __shfl_xor_sync(0xFFFFFFFFu, r2, off);
            r3 += __shfl_xor_sync(0xFFFFFFFFu, r3, off);
        }
        if (lane < 8) {
            float4 sk = reinterpret_cast<const float4*>(g_skip)[n * 8 + q];
            float4 o;
            o.x = fmaf(0.25f, r0, bg4.x + sk.x);
            o.y = fmaf(0.25f, r1, bg4.y + sk.y);
            o.z = fmaf(0.25f, r2, bg4.z + sk.z);
            o.w = fmaf(0.25f, r3, bg4.w + sk.w);
            reinterpret_cast<float4*>(out)[n * 8 + q] = o;
        }
    }
}

// ---------------- launch ----------------
extern "C" void kernel_launch(void* const* d_in, const int* in_sizes, int n_in,
                              void* d_out, int out_size) {
    const float* x   = (const float*)d_in[0];
    const int*   ei  = (const int*)  d_in[1];
    const float* ew  = (const float*)d_in[2];
    const float* W1  = (const float*)d_in[3];
    const float* b1  = (const float*)d_in[4];
    const float* Wl  = (const float*)d_in[5];
    const float* bl  = (const float*)d_in[6];
    const float* Wr  = (const float*)d_in[7];
    const float* br  = (const float*)d_in[8];
    const float* We  = (const float*)d_in[9];
    const float* att = (const float*)d_in[10];
    const float* bg  = (const float*)d_in[11];
    const float* Ws  = (const float*)d_in[12];
    const float* bs  = (const float*)d_in[13];
    const float* sg  = (const float*)d_in[14];
    float* out = (float*)d_out;

    const int* src = ei;
    const int* dst = ei + EE;

    void *p_hx, *p_h2, *p_xl, *p_xr, *p_skip;
    cudaGetSymbolAddress(&p_hx, g_hx);
    cudaGetSymbolAddress(&p_h2, g_h2);
    cudaGetSymbolAddress(&p_xl, g_xl);
    cudaGetSymbolAddress(&p_xr, g_xr);
    cudaGetSymbolAddress(&p_skip, g_skip);

    zero_kernel<<<128, 256>>>();
    gemm64<64, 16, 4><<<1024, dim3(64, 4)>>>(x, W1, nullptr, nullptr, (float*)p_hx, NN);
    gemm64<32, 32, 8><<<1024, dim3(32, 8)>>>(x, Ws, bs, sg, (float*)p_skip, NN);
    deg_kernel<<<800, 256>>>(dst, ew);
    node_kernel<<<128, 256>>>();
    scan_kernel<<<1, 1024>>>();
    csr_kernel<<<800, 256>>>(src, dst, ew);
    gcn_kernel<<<1184, 256>>>(b1);
    gemm64<128, 8, 2><<<1024, dim3(128, 2)>>>((const float*)p_h2, Wl, bl, nullptr, (float*)p_xl, NN);
    gemm64<128, 8, 2><<<1024, dim3(128, 2)>>>((const float*)p_h2, Wr, br, nullptr, (float*)p_xr, NN);
    gat_kernel<<<1184, 256>>>(We, att, bg, out);
}